// round 1
// baseline (speedup 1.0000x reference)
#include <cuda_runtime.h>
#include <math.h>

// Problem constants (fixed by the dataset: input [8,2048,768], W [768,768])
constexpr int D = 768;
constexpr int S = 2048;
constexpr int BMAX = 8;

// Scratch (no allocations allowed -> __device__ globals)
__device__ float g_M[D * D];          // Wq @ Wk^T
__device__ float g_G[BMAX * D * D];   // X_b^T @ X_b
__device__ float g_H[BMAX * D * D];   // (M @ G_b) / c

// ---------------------------------------------------------------------------
// Tiled SGEMM: C[M x N] (row-major) = alpha * op(A) * op(B)
//   TA=false: A is [M x K] row-major;  TA=true: A is [K x M] row-major
//   TB=false: B is [K x N] row-major;  TB=true: B is [N x K] row-major
// 64x64 block tile, 16-deep K tiles, 256 threads, 4x4 per-thread tile.
// blockIdx.z selects batch via element strides sA/sB/sC.
// All dims must be multiples of 64 (M,N) and 16 (K), pointers 16B-aligned.
// ---------------------------------------------------------------------------
constexpr int TS = 64;
constexpr int KS = 16;

template <bool TA, bool TB>
__global__ __launch_bounds__(256) void sgemm_kernel(
    const float* __restrict__ Ab, const float* __restrict__ Bb,
    float* __restrict__ Cb, int M, int N, int K,
    long long sA, long long sB, long long sC, float alpha)
{
    const float* A = Ab + (long long)blockIdx.z * sA;
    const float* B = Bb + (long long)blockIdx.z * sB;
    float* C = Cb + (long long)blockIdx.z * sC;

    __shared__ float As[KS][TS];  // As[k][m]
    __shared__ float Bs[KS][TS];  // Bs[k][n]

    const int tid = threadIdx.x;          // 0..255
    const int tx = tid % 16;              // n-tile coord
    const int ty = tid / 16;              // m-tile coord
    const int m0 = blockIdx.y * TS;
    const int n0 = blockIdx.x * TS;

    float acc[4][4] = {};

    for (int k0 = 0; k0 < K; k0 += KS) {
        // ---- load A tile into As[k][m] ----
        if (TA) {
            // A: [K x M], row contiguous along m -> direct, fully coalesced
            const int lm = (tid % 16) * 4;   // 0..60
            const int lk = tid / 16;         // 0..15
            const float4 v = *reinterpret_cast<const float4*>(
                A + (long long)(k0 + lk) * M + m0 + lm);
            As[lk][lm + 0] = v.x; As[lk][lm + 1] = v.y;
            As[lk][lm + 2] = v.z; As[lk][lm + 3] = v.w;
        } else {
            // A: [M x K], contiguous along k -> transpose into shared
            const int lk = (tid % 4) * 4;    // 0,4,8,12
            const int lm = tid / 4;          // 0..63
            const float4 v = *reinterpret_cast<const float4*>(
                A + (long long)(m0 + lm) * K + k0 + lk);
            As[lk + 0][lm] = v.x; As[lk + 1][lm] = v.y;
            As[lk + 2][lm] = v.z; As[lk + 3][lm] = v.w;
        }
        // ---- load B tile into Bs[k][n] ----
        if (TB) {
            // B: [N x K], contiguous along k -> transpose into shared
            const int lk = (tid % 4) * 4;
            const int ln = tid / 4;
            const float4 v = *reinterpret_cast<const float4*>(
                B + (long long)(n0 + ln) * K + k0 + lk);
            Bs[lk + 0][ln] = v.x; Bs[lk + 1][ln] = v.y;
            Bs[lk + 2][ln] = v.z; Bs[lk + 3][ln] = v.w;
        } else {
            // B: [K x N], contiguous along n -> direct, fully coalesced
            const int ln = (tid % 16) * 4;
            const int lk = tid / 16;
            const float4 v = *reinterpret_cast<const float4*>(
                B + (long long)(k0 + lk) * N + n0 + ln);
            Bs[lk][ln + 0] = v.x; Bs[lk][ln + 1] = v.y;
            Bs[lk][ln + 2] = v.z; Bs[lk][ln + 3] = v.w;
        }
        __syncthreads();

        #pragma unroll
        for (int k = 0; k < KS; k++) {
            const float4 av = *reinterpret_cast<const float4*>(&As[k][ty * 4]);
            const float4 bv = *reinterpret_cast<const float4*>(&Bs[k][tx * 4]);
            const float a[4] = {av.x, av.y, av.z, av.w};
            const float b[4] = {bv.x, bv.y, bv.z, bv.w};
            #pragma unroll
            for (int i = 0; i < 4; i++)
                #pragma unroll
                for (int j = 0; j < 4; j++)
                    acc[i][j] += a[i] * b[j];
        }
        __syncthreads();
    }

    // ---- write back ----
    #pragma unroll
    for (int i = 0; i < 4; i++) {
        const int m = m0 + ty * 4 + i;
        float4 v;
        v.x = acc[i][0] * alpha; v.y = acc[i][1] * alpha;
        v.z = acc[i][2] * alpha; v.w = acc[i][3] * alpha;
        *reinterpret_cast<float4*>(C + (long long)m * N + n0 + tx * 4) = v;
    }
}

extern "C" void kernel_launch(void* const* d_in, const int* in_sizes, int n_in,
                              void* d_out, int out_size)
{
    const float* X  = (const float*)d_in[0];  // [B,S,D]
    // d_in[1] = attention_mask (dead in the reference output)
    const float* Wq = (const float*)d_in[2];  // [D,D]
    const float* Wk = (const float*)d_in[3];  // [D,D]
    // d_in[4] = Wv (dead)
    float* out = (float*)d_out;               // [B,S,D]

    const int B = in_sizes[1];                // 8

    // Device-symbol addresses (resolved once on the eager correctness call;
    // the graph-capture call reuses the cached pointers -> capture-safe).
    static float* pM = nullptr;
    static float* pG = nullptr;
    static float* pH = nullptr;
    if (pM == nullptr) {
        cudaGetSymbolAddress((void**)&pM, g_M);
        cudaGetSymbolAddress((void**)&pG, g_G);
        cudaGetSymbolAddress((void**)&pH, g_H);
    }

    const float alpha = 1.0f / sqrtf((float)D * (float)D * (float)D);
    const long long DD = (long long)D * D;
    const long long SD = (long long)S * D;

    dim3 blk(256);

    // 1) M = Wq @ Wk^T            (NT)  [768x768]
    {
        dim3 grid(D / TS, D / TS, 1);
        sgemm_kernel<false, true><<<grid, blk>>>(Wq, Wk, pM, D, D, D, 0, 0, 0, 1.0f);
    }
    // 2) G_b = X_b^T @ X_b        (TN)  [768x768] x B, K = 2048
    {
        dim3 grid(D / TS, D / TS, B);
        sgemm_kernel<true, false><<<grid, blk>>>(X, X, pG, D, D, S, SD, SD, DD, 1.0f);
    }
    // 3) H_b = (M @ G_b) * alpha  (NN)  [768x768] x B
    {
        dim3 grid(D / TS, D / TS, B);
        sgemm_kernel<false, false><<<grid, blk>>>(pM, pG, pH, D, D, D, 0, DD, DD, alpha);
    }
    // 4) Out_b = X_b @ H_b        (NN)  [2048x768] x B
    {
        dim3 grid(D / TS, S / TS, B);
        sgemm_kernel<false, false><<<grid, blk>>>(X, pH, out, S, D, D, SD, DD, SD, 1.0f);
    }
}

// round 2
// speedup vs baseline: 1.1765x; 1.1765x over previous
#include <cuda_runtime.h>
#include <math.h>

constexpr int D = 768;
constexpr int S = 2048;
constexpr int BMAX = 8;

__device__ float g_M[D * D];          // Wq @ Wk^T
__device__ float g_G[BMAX * D * D];   // X_b^T @ X_b
__device__ float g_H[BMAX * D * D];   // (M @ G_b) / c

// ---------------------------------------------------------------------------
// 128x128x8 double-buffered SGEMM, 256 threads, 8x8 per-thread microtile.
// C[MxN] row-major = alpha * op(A) * op(B); strided batch via blockIdx.z.
//   TA=false: A [MxK] rm;  TA=true: A [KxM] rm
//   TB=false: B [KxN] rm;  TB=true: B [NxK] rm
// Requires: M,N multiples of 128; K multiple of 8; 16B-aligned pointers.
// ---------------------------------------------------------------------------
constexpr int BM = 128;
constexpr int BN = 128;
constexpr int BK = 8;
constexpr int PAD = 4;       // smem row pad (keeps float4 alignment: (BM+4)%4==0)
constexpr int LDA = BM + PAD;
constexpr int LDB = BN + PAD;

template <bool TA, bool TB>
__global__ __launch_bounds__(256) void sgemm128(
    const float* __restrict__ Ab, const float* __restrict__ Bb,
    float* __restrict__ Cb, int M, int N, int K,
    long long sA, long long sB, long long sC, float alpha)
{
    const float* A = Ab + (long long)blockIdx.z * sA;
    const float* B = Bb + (long long)blockIdx.z * sB;
    float* C = Cb + (long long)blockIdx.z * sC;

    __shared__ float As[2][BK][LDA];   // As[buf][k][m]
    __shared__ float Bs[2][BK][LDB];   // Bs[buf][k][n]

    const int tid = threadIdx.x;
    const int m0 = blockIdx.y * BM;
    const int n0 = blockIdx.x * BN;

    // ---- global-load index precompute ----
    // transpose-style loader (for [rows x K] source -> smem[k][row]):
    const int tr = tid >> 1;            // 0..127 (row within tile)
    const int tc = (tid & 1) * 4;       // 0 or 4 (k offset)
    // direct-style loader (for [K x cols] source -> smem[k][col]):
    const int dk = tid >> 5;            // 0..7
    const int dc = (tid & 31) * 4;      // 0..124

    const float* gA;
    const float* gB;
    if (TA) gA = A + (long long)dk * M + m0 + dc;           // [KxM]
    else    gA = A + (long long)(m0 + tr) * K + tc;          // [MxK]
    if (TB) gB = B + (long long)(n0 + tr) * K + tc;          // [NxK]
    else    gB = B + (long long)dk * N + n0 + dc;            // [KxN]

    const long long stepA = TA ? (long long)BK * M : BK;
    const long long stepB = TB ? BK : (long long)BK * N;

    auto storeA = [&](int buf, float4 v) {
        if (TA) {
            *reinterpret_cast<float4*>(&As[buf][dk][dc]) = v;
        } else {
            As[buf][tc + 0][tr] = v.x; As[buf][tc + 1][tr] = v.y;
            As[buf][tc + 2][tr] = v.z; As[buf][tc + 3][tr] = v.w;
        }
    };
    auto storeB = [&](int buf, float4 v) {
        if (TB) {
            Bs[buf][tc + 0][tr] = v.x; Bs[buf][tc + 1][tr] = v.y;
            Bs[buf][tc + 2][tr] = v.z; Bs[buf][tc + 3][tr] = v.w;
        } else {
            *reinterpret_cast<float4*>(&Bs[buf][dk][dc]) = v;
        }
    };

    // ---- prologue: load first tile ----
    {
        float4 va = *reinterpret_cast<const float4*>(gA);
        float4 vb = *reinterpret_cast<const float4*>(gB);
        storeA(0, va);
        storeB(0, vb);
    }
    __syncthreads();

    const int tx = tid & 15;            // n microtile
    const int ty = tid >> 4;            // m microtile
    const int ma = ty * 8;
    const int nb = tx * 8;

    float acc[8][8] = {};
    int buf = 0;

    for (int k0 = 0; k0 < K; k0 += BK) {
        const bool more = (k0 + BK) < K;
        float4 va, vb;
        if (more) {
            va = *reinterpret_cast<const float4*>(gA + stepA * ((k0 / BK) + 1));
            vb = *reinterpret_cast<const float4*>(gB + stepB * ((k0 / BK) + 1));
        }

        #pragma unroll
        for (int k = 0; k < BK; k++) {
            float a[8], b[8];
            *reinterpret_cast<float4*>(a)     = *reinterpret_cast<const float4*>(&As[buf][k][ma]);
            *reinterpret_cast<float4*>(a + 4) = *reinterpret_cast<const float4*>(&As[buf][k][ma + 4]);
            *reinterpret_cast<float4*>(b)     = *reinterpret_cast<const float4*>(&Bs[buf][k][nb]);
            *reinterpret_cast<float4*>(b + 4) = *reinterpret_cast<const float4*>(&Bs[buf][k][nb + 4]);
            #pragma unroll
            for (int i = 0; i < 8; i++)
                #pragma unroll
                for (int j = 0; j < 8; j++)
                    acc[i][j] = fmaf(a[i], b[j], acc[i][j]);
        }

        if (more) {
            storeA(buf ^ 1, va);
            storeB(buf ^ 1, vb);
            __syncthreads();
            buf ^= 1;
        }
    }

    // ---- epilogue ----
    #pragma unroll
    for (int i = 0; i < 8; i++) {
        const long long m = m0 + ma + i;
        float4 v0, v1;
        v0.x = acc[i][0] * alpha; v0.y = acc[i][1] * alpha;
        v0.z = acc[i][2] * alpha; v0.w = acc[i][3] * alpha;
        v1.x = acc[i][4] * alpha; v1.y = acc[i][5] * alpha;
        v1.z = acc[i][6] * alpha; v1.w = acc[i][7] * alpha;
        *reinterpret_cast<float4*>(C + m * N + n0 + nb)     = v0;
        *reinterpret_cast<float4*>(C + m * N + n0 + nb + 4) = v1;
    }
}

extern "C" void kernel_launch(void* const* d_in, const int* in_sizes, int n_in,
                              void* d_out, int out_size)
{
    const float* X  = (const float*)d_in[0];  // [B,S,D]
    const float* Wq = (const float*)d_in[2];  // [D,D]
    const float* Wk = (const float*)d_in[3];  // [D,D]
    float* out = (float*)d_out;               // [B,S,D]

    const int B = in_sizes[1];                // 8

    static float* pM = nullptr;
    static float* pG = nullptr;
    static float* pH = nullptr;
    if (pM == nullptr) {
        cudaGetSymbolAddress((void**)&pM, g_M);
        cudaGetSymbolAddress((void**)&pG, g_G);
        cudaGetSymbolAddress((void**)&pH, g_H);
    }

    const float alpha = 1.0f / sqrtf((float)D * (float)D * (float)D);
    const long long DD = (long long)D * D;
    const long long SD = (long long)S * D;

    dim3 blk(256);

    // 1) M = Wq @ Wk^T            (NT)  [768x768]
    {
        dim3 grid(D / BN, D / BM, 1);
        sgemm128<false, true><<<grid, blk>>>(Wq, Wk, pM, D, D, D, 0, 0, 0, 1.0f);
    }
    // 2) G_b = X_b^T @ X_b        (TN)  [768x768] x B, K = 2048
    {
        dim3 grid(D / BN, D / BM, B);
        sgemm128<true, false><<<grid, blk>>>(X, X, pG, D, D, S, SD, SD, DD, 1.0f);
    }
    // 3) H_b = (M @ G_b) * alpha  (NN)  [768x768] x B
    {
        dim3 grid(D / BN, D / BM, B);
        sgemm128<false, false><<<grid, blk>>>(pM, pG, pH, D, D, D, 0, DD, DD, alpha);
    }
    // 4) Out_b = X_b @ H_b        (NN)  [2048x768] x B
    {
        dim3 grid(D / BN, S / BM, B);
        sgemm128<false, false><<<grid, blk>>>(X, pH, out, S, D, D, SD, DD, SD, 1.0f);
    }
}

// round 4
// speedup vs baseline: 2.6184x; 2.2256x over previous
#include <cuda_runtime.h>
#include <cuda_bf16.h>
#include <math.h>
#include <stdint.h>

constexpr int D = 768;
constexpr int S = 2048;
constexpr int BMAX = 8;

// ---- bf16 hi/lo split operand storage (no cudaMalloc allowed) ----
__device__ __align__(256) __nv_bfloat16 g_Xhi[BMAX * S * D], g_Xlo[BMAX * S * D];
__device__ __align__(256) __nv_bfloat16 g_XThi[BMAX * D * S], g_XTlo[BMAX * D * S];
__device__ __align__(256) __nv_bfloat16 g_Qhi[D * D], g_Qlo[D * D];
__device__ __align__(256) __nv_bfloat16 g_Khi[D * D], g_Klo[D * D];
__device__ __align__(256) __nv_bfloat16 g_Mhi[D * D], g_Mlo[D * D];
__device__ __align__(256) __nv_bfloat16 g_Ghi[BMAX * D * D], g_Glo[BMAX * D * D];
__device__ __align__(256) __nv_bfloat16 g_Hhi[BMAX * D * D], g_Hlo[BMAX * D * D];

// ============================ helpers ============================
__device__ __forceinline__ uint32_t smem_u32(const void* p) {
    uint32_t a;
    asm("{ .reg .u64 t; cvta.to.shared.u64 t, %1; cvt.u32.u64 %0, t; }" : "=r"(a) : "l"(p));
    return a;
}
__device__ __forceinline__ void cp_async16(uint32_t dst, const void* src) {
    asm volatile("cp.async.cg.shared.global [%0], [%1], 16;" :: "r"(dst), "l"(src) : "memory");
}
#define CP_COMMIT() asm volatile("cp.async.commit_group;" ::: "memory")
template <int N>
__device__ __forceinline__ void cp_wait() {
    asm volatile("cp.async.wait_group %0;" :: "n"(N) : "memory");
}

__device__ __forceinline__ uint32_t pack_bf16(__nv_bfloat16 a, __nv_bfloat16 b) {
    return (uint32_t)__bfloat16_as_ushort(b) << 16 | (uint32_t)__bfloat16_as_ushort(a);
}

// m16n8k16 bf16 MMA, fp32 accum (plain-PTX path, lowers to HMMA on sm_103)
__device__ __forceinline__ void mma16816(float c[4], const uint32_t a[4],
                                         uint32_t b0, uint32_t b1) {
    asm volatile(
        "mma.sync.aligned.m16n8k16.row.col.f32.bf16.bf16.f32 "
        "{%0,%1,%2,%3}, {%4,%5,%6,%7}, {%8,%9}, {%0,%1,%2,%3};"
        : "+f"(c[0]), "+f"(c[1]), "+f"(c[2]), "+f"(c[3])
        : "r"(a[0]), "r"(a[1]), "r"(a[2]), "r"(a[3]), "r"(b0), "r"(b1));
}

// Tile pitch: 32 bf16 per row = 64B data, 80B pitch (stride-5 granules -> no
// ldmatrix bank conflicts: 5 coprime with 8).
constexpr int PITCH = 80;
constexpr int TILE_BYTES = 128 * PITCH;      // 10240
constexpr int STAGE_BYTES = 4 * TILE_BYTES;  // Ahi, Alo, Bhi, Blo
constexpr int SMEM_SZ = 2 * STAGE_BYTES;     // 81920

// A fragment m16k16 from smem tile (rows = m, 32 bf16 K-major per row)
__device__ __forceinline__ void ldmA(uint32_t base, int mrow, int kbyte, int lane, uint32_t r[4]) {
    const int q = lane >> 3;
    const uint32_t addr = base + (uint32_t)(mrow + (lane & 7) + ((q & 1) << 3)) * PITCH
                               + kbyte + ((q >> 1) << 4);
    asm volatile("ldmatrix.sync.aligned.m8n8.x4.shared.b16 {%0,%1,%2,%3}, [%4];"
                 : "=r"(r[0]), "=r"(r[1]), "=r"(r[2]), "=r"(r[3]) : "r"(addr));
}
// B fragments for two n8-tiles (n16 x k16); regs: {b0 t0, b1 t0, b0 t1, b1 t1}
__device__ __forceinline__ void ldmB(uint32_t base, int nrow, int kbyte, int lane, uint32_t r[4]) {
    const int q = lane >> 3;
    const uint32_t addr = base + (uint32_t)(nrow + (lane & 7) + ((q >> 1) << 3)) * PITCH
                               + kbyte + ((q & 1) << 4);
    asm volatile("ldmatrix.sync.aligned.m8n8.x4.shared.b16 {%0,%1,%2,%3}, [%4];"
                 : "=r"(r[0]), "=r"(r[1]), "=r"(r[2]), "=r"(r[3]) : "r"(addr));
}

// load one 128x32 bf16 K-chunk into smem tile (16B granules)
__device__ __forceinline__ void load_tile_g(uint32_t sbase, const __nv_bfloat16* src,
                                            int K, int kc, int tid) {
    const char* s0 = reinterpret_cast<const char*>(src) + (size_t)kc * 64;
    const size_t rs = (size_t)K * 2;
    #pragma unroll
    for (int i = tid; i < 512; i += 256) {
        const int row = i >> 2, g = i & 3;
        cp_async16(sbase + row * PITCH + g * 16, s0 + (size_t)row * rs + g * 16);
    }
}

// ======================= split / transpose kernels =======================
__global__ __launch_bounds__(256) void split_kernel(
    const float* __restrict__ x, __nv_bfloat16* __restrict__ hi,
    __nv_bfloat16* __restrict__ lo, int n4)
{
    int i = blockIdx.x * blockDim.x + threadIdx.x;
    if (i >= n4) return;
    float4 v = reinterpret_cast<const float4*>(x)[i];
    float a[4] = {v.x, v.y, v.z, v.w};
    uint32_t ph[2], pl[2];
    #pragma unroll
    for (int p = 0; p < 2; p++) {
        __nv_bfloat16 h0 = __float2bfloat16(a[2 * p]);
        __nv_bfloat16 h1 = __float2bfloat16(a[2 * p + 1]);
        __nv_bfloat16 l0 = __float2bfloat16(a[2 * p] - __bfloat162float(h0));
        __nv_bfloat16 l1 = __float2bfloat16(a[2 * p + 1] - __bfloat162float(h1));
        ph[p] = pack_bf16(h0, h1);
        pl[p] = pack_bf16(l0, l1);
    }
    reinterpret_cast<uint2*>(hi)[i] = make_uint2(ph[0], ph[1]);
    reinterpret_cast<uint2*>(lo)[i] = make_uint2(pl[0], pl[1]);
}

__global__ __launch_bounds__(256) void transplit_kernel(
    const float* __restrict__ X, __nv_bfloat16* __restrict__ XThi,
    __nv_bfloat16* __restrict__ XTlo)
{
    __shared__ float t[32][33];
    const int b = blockIdx.z;
    const int s0 = blockIdx.x * 32, d0 = blockIdx.y * 32;
    const int tx = threadIdx.x & 31, ty = threadIdx.x >> 5;
    const float* Xb = X + (size_t)b * S * D;
    #pragma unroll
    for (int i = 0; i < 32; i += 8)
        t[ty + i][tx] = Xb[(size_t)(s0 + ty + i) * D + d0 + tx];
    __syncthreads();
    __nv_bfloat16* hb = XThi + (size_t)b * D * S;
    __nv_bfloat16* lb = XTlo + (size_t)b * D * S;
    #pragma unroll
    for (int i = 0; i < 32; i += 8) {
        float v = t[tx][ty + i];
        __nv_bfloat16 h = __float2bfloat16(v);
        __nv_bfloat16 l = __float2bfloat16(v - __bfloat162float(h));
        size_t o = (size_t)(d0 + ty + i) * S + s0 + tx;
        hb[o] = h;
        lb[o] = l;
    }
}

// ======================= split-bf16 MMA GEMM =======================
// C[m][n] = alpha * sum_k A[m][k]*B[n][k]; A [MxK] rows, B [NxK] rows (K-major)
// 3 passes into shared fp32 acc: Ahi*Bhi + Ahi*Blo + Alo*Bhi.
// CTA tile 128x128, BK=32, 8 warps of 64x32. EPI=0 fp32 out, EPI=1 hi/lo bf16.
template <int EPI>
__global__ __launch_bounds__(256, 2) void mma_gemm(
    const __nv_bfloat16* __restrict__ Ahi_, const __nv_bfloat16* __restrict__ Alo_,
    const __nv_bfloat16* __restrict__ Bhi_, const __nv_bfloat16* __restrict__ Blo_,
    float* __restrict__ outF, __nv_bfloat16* __restrict__ outHi,
    __nv_bfloat16* __restrict__ outLo,
    int K, int ldC, long long sA, long long sB, long long sC, float alpha)
{
    extern __shared__ __align__(128) char smem[];
    const uint32_t sb = smem_u32(smem);
    const int tid = threadIdx.x;
    const int lane = tid & 31, wid = tid >> 5;
    const int wm = wid & 1;        // 2 m-slots of 64
    const int wn = wid >> 1;       // 4 n-slots of 32

    const size_t zb = blockIdx.z;
    const int m0 = blockIdx.y * 128, n0 = blockIdx.x * 128;
    const __nv_bfloat16* Ahi = Ahi_ + zb * sA + (size_t)m0 * K;
    const __nv_bfloat16* Alo = Alo_ + zb * sA + (size_t)m0 * K;
    const __nv_bfloat16* Bhi = Bhi_ + zb * sB + (size_t)n0 * K;
    const __nv_bfloat16* Blo = Blo_ + zb * sB + (size_t)n0 * K;

    float acc[4][4][4] = {};   // [mt][nt][frag]

    auto issue = [&](int stage, int kc) {
        const uint32_t s = sb + stage * STAGE_BYTES;
        load_tile_g(s,                  Ahi, K, kc, tid);
        load_tile_g(s + TILE_BYTES,     Alo, K, kc, tid);
        load_tile_g(s + 2 * TILE_BYTES, Bhi, K, kc, tid);
        load_tile_g(s + 3 * TILE_BYTES, Blo, K, kc, tid);
        CP_COMMIT();
    };

    const int KC = K >> 5;
    issue(0, 0);

    for (int kc = 0; kc < KC; kc++) {
        const int st = kc & 1;
        const bool more = (kc + 1) < KC;
        if (more) issue(st ^ 1, kc + 1);
        if (more) cp_wait<1>(); else cp_wait<0>();
        __syncthreads();

        const uint32_t sAhi = sb + st * STAGE_BYTES;
        const uint32_t sAlo = sAhi + TILE_BYTES;
        const uint32_t sBhi = sAhi + 2 * TILE_BYTES;
        const uint32_t sBlo = sAhi + 3 * TILE_BYTES;
        const int nrow = wn * 32;

        #pragma unroll
        for (int ks = 0; ks < 2; ks++) {
            const int kbyte = ks * 32;
            uint32_t bh[2][4], bl[2][4];
            ldmB(sBhi, nrow,      kbyte, lane, bh[0]);
            ldmB(sBhi, nrow + 16, kbyte, lane, bh[1]);
            ldmB(sBlo, nrow,      kbyte, lane, bl[0]);
            ldmB(sBlo, nrow + 16, kbyte, lane, bl[1]);
            #pragma unroll
            for (int mt = 0; mt < 4; mt++) {
                uint32_t ah[4], al[4];
                ldmA(sAhi, wm * 64 + mt * 16, kbyte, lane, ah);
                ldmA(sAlo, wm * 64 + mt * 16, kbyte, lane, al);
                #pragma unroll
                for (int nt = 0; nt < 4; nt++) {
                    const uint32_t b0h = bh[nt >> 1][(nt & 1) * 2];
                    const uint32_t b1h = bh[nt >> 1][(nt & 1) * 2 + 1];
                    const uint32_t b0l = bl[nt >> 1][(nt & 1) * 2];
                    const uint32_t b1l = bl[nt >> 1][(nt & 1) * 2 + 1];
                    mma16816(acc[mt][nt], ah, b0h, b1h);
                    mma16816(acc[mt][nt], ah, b0l, b1l);
                    mma16816(acc[mt][nt], al, b0h, b1h);
                }
            }
        }
        __syncthreads();
    }

    // ---- epilogue ----
    const int r0 = lane >> 2;
    const int c0 = (lane & 3) * 2;
    #pragma unroll
    for (int mt = 0; mt < 4; mt++) {
        #pragma unroll
        for (int half = 0; half < 2; half++) {
            const size_t m = (size_t)(m0 + wm * 64 + mt * 16 + r0 + half * 8);
            #pragma unroll
            for (int nt = 0; nt < 4; nt++) {
                const size_t n = (size_t)(n0 + wn * 32 + nt * 8 + c0);
                const float v0 = acc[mt][nt][half * 2 + 0] * alpha;
                const float v1 = acc[mt][nt][half * 2 + 1] * alpha;
                if (EPI == 0) {
                    float2 v = make_float2(v0, v1);
                    *reinterpret_cast<float2*>(outF + zb * sC + m * ldC + n) = v;
                } else {
                    __nv_bfloat16 h0 = __float2bfloat16(v0);
                    __nv_bfloat16 h1 = __float2bfloat16(v1);
                    __nv_bfloat16 l0 = __float2bfloat16(v0 - __bfloat162float(h0));
                    __nv_bfloat16 l1 = __float2bfloat16(v1 - __bfloat162float(h1));
                    const size_t o = zb * sC + m * ldC + n;
                    *reinterpret_cast<uint32_t*>(outHi + o) = pack_bf16(h0, h1);
                    *reinterpret_cast<uint32_t*>(outLo + o) = pack_bf16(l0, l1);
                }
            }
        }
    }
}

// ============================== launcher ==============================
extern "C" void kernel_launch(void* const* d_in, const int* in_sizes, int n_in,
                              void* d_out, int out_size)
{
    const float* X  = (const float*)d_in[0];
    const float* Wq = (const float*)d_in[2];
    const float* Wk = (const float*)d_in[3];
    float* out = (float*)d_out;
    const int B = in_sizes[1];  // 8

    struct Ptrs {
        __nv_bfloat16 *Xhi, *Xlo, *XThi, *XTlo, *Qhi, *Qlo, *Khi, *Klo;
        __nv_bfloat16 *Mhi, *Mlo, *Ghi, *Glo, *Hhi, *Hlo;
    };
    static Ptrs p;
    static bool inited = false;
    if (!inited) {
        cudaGetSymbolAddress((void**)&p.Xhi, g_Xhi);
        cudaGetSymbolAddress((void**)&p.Xlo, g_Xlo);
        cudaGetSymbolAddress((void**)&p.XThi, g_XThi);
        cudaGetSymbolAddress((void**)&p.XTlo, g_XTlo);
        cudaGetSymbolAddress((void**)&p.Qhi, g_Qhi);
        cudaGetSymbolAddress((void**)&p.Qlo, g_Qlo);
        cudaGetSymbolAddress((void**)&p.Khi, g_Khi);
        cudaGetSymbolAddress((void**)&p.Klo, g_Klo);
        cudaGetSymbolAddress((void**)&p.Mhi, g_Mhi);
        cudaGetSymbolAddress((void**)&p.Mlo, g_Mlo);
        cudaGetSymbolAddress((void**)&p.Ghi, g_Ghi);
        cudaGetSymbolAddress((void**)&p.Glo, g_Glo);
        cudaGetSymbolAddress((void**)&p.Hhi, g_Hhi);
        cudaGetSymbolAddress((void**)&p.Hlo, g_Hlo);
        cudaFuncSetAttribute(mma_gemm<0>, cudaFuncAttributeMaxDynamicSharedMemorySize, SMEM_SZ);
        cudaFuncSetAttribute(mma_gemm<1>, cudaFuncAttributeMaxDynamicSharedMemorySize, SMEM_SZ);
        inited = true;
    }

    const float alpha = 1.0f / sqrtf((float)D * (float)D * (float)D);
    const long long DD = (long long)D * D;
    const long long SD = (long long)S * D;

    // operand splits
    {
        int n4 = B * S * D / 4;
        split_kernel<<<(n4 + 255) / 256, 256>>>(X, p.Xhi, p.Xlo, n4);
    }
    {
        dim3 g(S / 32, D / 32, B);
        transplit_kernel<<<g, 256>>>(X, p.XThi, p.XTlo);
    }
    {
        int n4 = D * D / 4;
        split_kernel<<<(n4 + 255) / 256, 256>>>(Wq, p.Qhi, p.Qlo, n4);
        split_kernel<<<(n4 + 255) / 256, 256>>>(Wk, p.Khi, p.Klo, n4);
    }

    // 1) M = Wq @ Wk^T            [768x768], K=768
    mma_gemm<1><<<dim3(D / 128, D / 128, 1), 256, SMEM_SZ>>>(
        p.Qhi, p.Qlo, p.Khi, p.Klo, nullptr, p.Mhi, p.Mlo, D, D, 0, 0, 0, 1.0f);
    // 2) G_b = XT_b @ XT_b^T      [768x768] x B, K=2048
    mma_gemm<1><<<dim3(D / 128, D / 128, B), 256, SMEM_SZ>>>(
        p.XThi, p.XTlo, p.XThi, p.XTlo, nullptr, p.Ghi, p.Glo, S, D, SD, SD, DD, 1.0f);
    // 3) H^T_b = (G_b @ M^T) * alpha  [768x768] x B, K=768
    mma_gemm<1><<<dim3(D / 128, D / 128, B), 256, SMEM_SZ>>>(
        p.Ghi, p.Glo, p.Mhi, p.Mlo, nullptr, p.Hhi, p.Hlo, D, D, DD, 0, DD, alpha);
    // 4) Out_b = X_b @ (H^T_b)^T  [2048x768] x B, K=768
    mma_gemm<0><<<dim3(D / 128, S / 128, B), 256, SMEM_SZ>>>(
        p.Xhi, p.Xlo, p.Hhi, p.Hlo, out, nullptr, nullptr, D, D, SD, DD, SD, 1.0f);
}

// round 5
// speedup vs baseline: 2.6346x; 1.0062x over previous
#include <cuda_runtime.h>
#include <cuda_bf16.h>
#include <math.h>
#include <stdint.h>

constexpr int D = 768;
constexpr int S = 2048;
constexpr int BMAX = 8;

// ---- bf16 hi/lo split operand storage (no cudaMalloc allowed) ----
__device__ __align__(256) __nv_bfloat16 g_Xhi[BMAX * S * D], g_Xlo[BMAX * S * D];
__device__ __align__(256) __nv_bfloat16 g_XThi[BMAX * D * S], g_XTlo[BMAX * D * S];
__device__ __align__(256) __nv_bfloat16 g_Qhi[D * D], g_Qlo[D * D];
__device__ __align__(256) __nv_bfloat16 g_Khi[D * D], g_Klo[D * D];
__device__ __align__(256) __nv_bfloat16 g_Mhi[D * D], g_Mlo[D * D];
__device__ __align__(256) __nv_bfloat16 g_Ghi[BMAX * D * D], g_Glo[BMAX * D * D];
__device__ __align__(256) __nv_bfloat16 g_Hhi[BMAX * D * D], g_Hlo[BMAX * D * D];

// ============================ helpers ============================
__device__ __forceinline__ uint32_t smem_u32(const void* p) {
    uint32_t a;
    asm("{ .reg .u64 t; cvta.to.shared.u64 t, %1; cvt.u32.u64 %0, t; }" : "=r"(a) : "l"(p));
    return a;
}
__device__ __forceinline__ void cp_async16(uint32_t dst, const void* src) {
    asm volatile("cp.async.cg.shared.global [%0], [%1], 16;" :: "r"(dst), "l"(src) : "memory");
}
#define CP_COMMIT() asm volatile("cp.async.commit_group;" ::: "memory")
template <int N>
__device__ __forceinline__ void cp_wait() {
    asm volatile("cp.async.wait_group %0;" :: "n"(N) : "memory");
}

__device__ __forceinline__ uint32_t pack_bf16(__nv_bfloat16 a, __nv_bfloat16 b) {
    return (uint32_t)__bfloat16_as_ushort(b) << 16 | (uint32_t)__bfloat16_as_ushort(a);
}

// m16n8k16 bf16 MMA, fp32 accum (plain-PTX path, lowers to HMMA on sm_103)
__device__ __forceinline__ void mma16816(float c[4], const uint32_t a[4],
                                         uint32_t b0, uint32_t b1) {
    asm volatile(
        "mma.sync.aligned.m16n8k16.row.col.f32.bf16.bf16.f32 "
        "{%0,%1,%2,%3}, {%4,%5,%6,%7}, {%8,%9}, {%0,%1,%2,%3};"
        : "+f"(c[0]), "+f"(c[1]), "+f"(c[2]), "+f"(c[3])
        : "r"(a[0]), "r"(a[1]), "r"(a[2]), "r"(a[3]), "r"(b0), "r"(b1));
}

// Tile pitch: 32 bf16 per row = 64B data, 80B pitch (stride-5 granules -> no
// ldmatrix bank conflicts: 5 coprime with 8).
constexpr int PITCH = 80;
constexpr int TILE_BYTES = 128 * PITCH;      // 10240
constexpr int STAGE_BYTES = 4 * TILE_BYTES;  // Ahi, Alo, Bhi, Blo
constexpr int SMEM_SZ = 2 * STAGE_BYTES;     // 81920

__device__ __forceinline__ void ldmA(uint32_t base, int mrow, int kbyte, int lane, uint32_t r[4]) {
    const int q = lane >> 3;
    const uint32_t addr = base + (uint32_t)(mrow + (lane & 7) + ((q & 1) << 3)) * PITCH
                               + kbyte + ((q >> 1) << 4);
    asm volatile("ldmatrix.sync.aligned.m8n8.x4.shared.b16 {%0,%1,%2,%3}, [%4];"
                 : "=r"(r[0]), "=r"(r[1]), "=r"(r[2]), "=r"(r[3]) : "r"(addr));
}
__device__ __forceinline__ void ldmB(uint32_t base, int nrow, int kbyte, int lane, uint32_t r[4]) {
    const int q = lane >> 3;
    const uint32_t addr = base + (uint32_t)(nrow + (lane & 7) + ((q >> 1) << 3)) * PITCH
                               + kbyte + ((q & 1) << 4);
    asm volatile("ldmatrix.sync.aligned.m8n8.x4.shared.b16 {%0,%1,%2,%3}, [%4];"
                 : "=r"(r[0]), "=r"(r[1]), "=r"(r[2]), "=r"(r[3]) : "r"(addr));
}

// load one 128x32 bf16 K-chunk into smem tile (16B granules)
__device__ __forceinline__ void load_tile_g(uint32_t sbase, const __nv_bfloat16* src,
                                            int K, int kc, int tid) {
    const char* s0 = reinterpret_cast<const char*>(src) + (size_t)kc * 64;
    const size_t rs = (size_t)K * 2;
    #pragma unroll
    for (int i = tid; i < 512; i += 256) {
        const int row = i >> 2, g = i & 3;
        cp_async16(sbase + row * PITCH + g * 16, s0 + (size_t)row * rs + g * 16);
    }
}

// ======================= split / transpose kernels =======================
__global__ __launch_bounds__(256) void split_kernel(
    const float* __restrict__ x, __nv_bfloat16* __restrict__ hi,
    __nv_bfloat16* __restrict__ lo, int n4)
{
    int i = blockIdx.x * blockDim.x + threadIdx.x;
    if (i >= n4) return;
    float4 v = reinterpret_cast<const float4*>(x)[i];
    float a[4] = {v.x, v.y, v.z, v.w};
    uint32_t ph[2], pl[2];
    #pragma unroll
    for (int p = 0; p < 2; p++) {
        __nv_bfloat16 h0 = __float2bfloat16(a[2 * p]);
        __nv_bfloat16 h1 = __float2bfloat16(a[2 * p + 1]);
        __nv_bfloat16 l0 = __float2bfloat16(a[2 * p] - __bfloat162float(h0));
        __nv_bfloat16 l1 = __float2bfloat16(a[2 * p + 1] - __bfloat162float(h1));
        ph[p] = pack_bf16(h0, h1);
        pl[p] = pack_bf16(l0, l1);
    }
    reinterpret_cast<uint2*>(hi)[i] = make_uint2(ph[0], ph[1]);
    reinterpret_cast<uint2*>(lo)[i] = make_uint2(pl[0], pl[1]);
}

// X [B][S][D] fp32 -> Xhi/Xlo [B][S][D] AND XThi/XTlo [B][D][S] in one pass
__global__ __launch_bounds__(256) void transplit_kernel(
    const float* __restrict__ X,
    __nv_bfloat16* __restrict__ Xhi, __nv_bfloat16* __restrict__ Xlo,
    __nv_bfloat16* __restrict__ XThi, __nv_bfloat16* __restrict__ XTlo)
{
    __shared__ float t[32][33];
    const int b = blockIdx.z;
    const int s0 = blockIdx.x * 32, d0 = blockIdx.y * 32;
    const int tx = threadIdx.x & 31, ty = threadIdx.x >> 5;
    const float* Xb = X + (size_t)b * S * D;
    __nv_bfloat16* xh = Xhi + (size_t)b * S * D;
    __nv_bfloat16* xl = Xlo + (size_t)b * S * D;
    #pragma unroll
    for (int i = 0; i < 32; i += 8) {
        const size_t o = (size_t)(s0 + ty + i) * D + d0 + tx;
        float v = Xb[o];
        t[ty + i][tx] = v;
        __nv_bfloat16 h = __float2bfloat16(v);
        __nv_bfloat16 l = __float2bfloat16(v - __bfloat162float(h));
        xh[o] = h;
        xl[o] = l;
    }
    __syncthreads();
    __nv_bfloat16* hb = XThi + (size_t)b * D * S;
    __nv_bfloat16* lb = XTlo + (size_t)b * D * S;
    #pragma unroll
    for (int i = 0; i < 32; i += 8) {
        float v = t[tx][ty + i];
        __nv_bfloat16 h = __float2bfloat16(v);
        __nv_bfloat16 l = __float2bfloat16(v - __bfloat162float(h));
        size_t o = (size_t)(d0 + ty + i) * S + s0 + tx;
        hb[o] = h;
        lb[o] = l;
    }
}

// ======================= split-bf16 MMA GEMM =======================
// C[m][n] = alpha * sum_k A[m][k]*B[n][k]; A [MxK] rows, B [NxK] rows (K-major)
// 3 passes into shared fp32 acc: Ahi*Bhi + Ahi*Blo + Alo*Bhi.
// CTA tile 128x128, BK=32, 8 warps of 64x32. EPI=0 fp32 out, EPI=1 hi/lo bf16.
// MIRROR=true (with EPI=1): symmetric C — CTAs with bx>by exit; bx<by tiles
// also write the transposed tile.
template <int EPI, bool MIRROR>
__global__ __launch_bounds__(256, 2) void mma_gemm(
    const __nv_bfloat16* __restrict__ Ahi_, const __nv_bfloat16* __restrict__ Alo_,
    const __nv_bfloat16* __restrict__ Bhi_, const __nv_bfloat16* __restrict__ Blo_,
    float* __restrict__ outF, __nv_bfloat16* __restrict__ outHi,
    __nv_bfloat16* __restrict__ outLo,
    int K, int ldC, long long sA, long long sB, long long sC, float alpha)
{
    if (MIRROR && blockIdx.x > blockIdx.y) return;

    extern __shared__ __align__(128) char smem[];
    const uint32_t sb = smem_u32(smem);
    const int tid = threadIdx.x;
    const int lane = tid & 31, wid = tid >> 5;
    const int wm = wid & 1;        // 2 m-slots of 64
    const int wn = wid >> 1;       // 4 n-slots of 32

    const size_t zb = blockIdx.z;
    const int m0 = blockIdx.y * 128, n0 = blockIdx.x * 128;
    const __nv_bfloat16* Ahi = Ahi_ + zb * sA + (size_t)m0 * K;
    const __nv_bfloat16* Alo = Alo_ + zb * sA + (size_t)m0 * K;
    const __nv_bfloat16* Bhi = Bhi_ + zb * sB + (size_t)n0 * K;
    const __nv_bfloat16* Blo = Blo_ + zb * sB + (size_t)n0 * K;

    float acc[4][4][4] = {};   // [mt][nt][frag]

    auto issue = [&](int stage, int kc) {
        const uint32_t s = sb + stage * STAGE_BYTES;
        load_tile_g(s,                  Ahi, K, kc, tid);
        load_tile_g(s + TILE_BYTES,     Alo, K, kc, tid);
        load_tile_g(s + 2 * TILE_BYTES, Bhi, K, kc, tid);
        load_tile_g(s + 3 * TILE_BYTES, Blo, K, kc, tid);
        CP_COMMIT();
    };

    const int KC = K >> 5;
    issue(0, 0);

    for (int kc = 0; kc < KC; kc++) {
        const int st = kc & 1;
        const bool more = (kc + 1) < KC;
        if (more) issue(st ^ 1, kc + 1);
        if (more) cp_wait<1>(); else cp_wait<0>();
        __syncthreads();

        const uint32_t sAhi = sb + st * STAGE_BYTES;
        const uint32_t sAlo = sAhi + TILE_BYTES;
        const uint32_t sBhi = sAhi + 2 * TILE_BYTES;
        const uint32_t sBlo = sAhi + 3 * TILE_BYTES;
        const int nrow = wn * 32;

        #pragma unroll
        for (int ks = 0; ks < 2; ks++) {
            const int kbyte = ks * 32;
            uint32_t bh[2][4], bl[2][4];
            ldmB(sBhi, nrow,      kbyte, lane, bh[0]);
            ldmB(sBhi, nrow + 16, kbyte, lane, bh[1]);
            ldmB(sBlo, nrow,      kbyte, lane, bl[0]);
            ldmB(sBlo, nrow + 16, kbyte, lane, bl[1]);
            #pragma unroll
            for (int mt = 0; mt < 4; mt++) {
                uint32_t ah[4], al[4];
                ldmA(sAhi, wm * 64 + mt * 16, kbyte, lane, ah);
                ldmA(sAlo, wm * 64 + mt * 16, kbyte, lane, al);
                #pragma unroll
                for (int nt = 0; nt < 4; nt++) {
                    const uint32_t b0h = bh[nt >> 1][(nt & 1) * 2];
                    const uint32_t b1h = bh[nt >> 1][(nt & 1) * 2 + 1];
                    const uint32_t b0l = bl[nt >> 1][(nt & 1) * 2];
                    const uint32_t b1l = bl[nt >> 1][(nt & 1) * 2 + 1];
                    mma16816(acc[mt][nt], ah, b0h, b1h);
                    mma16816(acc[mt][nt], ah, b0l, b1l);
                    mma16816(acc[mt][nt], al, b0h, b1h);
                }
            }
        }
        __syncthreads();
    }

    // ---- epilogue ----
    const int r0 = lane >> 2;
    const int c0 = (lane & 3) * 2;
    const bool mir = MIRROR && (blockIdx.x != blockIdx.y);
    #pragma unroll
    for (int mt = 0; mt < 4; mt++) {
        #pragma unroll
        for (int half = 0; half < 2; half++) {
            const size_t m = (size_t)(m0 + wm * 64 + mt * 16 + r0 + half * 8);
            #pragma unroll
            for (int nt = 0; nt < 4; nt++) {
                const size_t n = (size_t)(n0 + wn * 32 + nt * 8 + c0);
                const float v0 = acc[mt][nt][half * 2 + 0] * alpha;
                const float v1 = acc[mt][nt][half * 2 + 1] * alpha;
                if (EPI == 0) {
                    float2 v = make_float2(v0, v1);
                    *reinterpret_cast<float2*>(outF + zb * sC + m * ldC + n) = v;
                } else {
                    __nv_bfloat16 h0 = __float2bfloat16(v0);
                    __nv_bfloat16 h1 = __float2bfloat16(v1);
                    __nv_bfloat16 l0 = __float2bfloat16(v0 - __bfloat162float(h0));
                    __nv_bfloat16 l1 = __float2bfloat16(v1 - __bfloat162float(h1));
                    const size_t o = zb * sC + m * ldC + n;
                    *reinterpret_cast<uint32_t*>(outHi + o) = pack_bf16(h0, h1);
                    *reinterpret_cast<uint32_t*>(outLo + o) = pack_bf16(l0, l1);
                    if (mir) {
                        const size_t ot = zb * sC + n * ldC + m;
                        outHi[ot] = h0;          outLo[ot] = l0;
                        outHi[ot + ldC] = h1;    outLo[ot + ldC] = l1;
                    }
                }
            }
        }
    }
}

// ============================== launcher ==============================
extern "C" void kernel_launch(void* const* d_in, const int* in_sizes, int n_in,
                              void* d_out, int out_size)
{
    const float* X  = (const float*)d_in[0];
    const float* Wq = (const float*)d_in[2];
    const float* Wk = (const float*)d_in[3];
    float* out = (float*)d_out;
    const int B = in_sizes[1];  // 8

    struct Ptrs {
        __nv_bfloat16 *Xhi, *Xlo, *XThi, *XTlo, *Qhi, *Qlo, *Khi, *Klo;
        __nv_bfloat16 *Mhi, *Mlo, *Ghi, *Glo, *Hhi, *Hlo;
    };
    static Ptrs p;
    static bool inited = false;
    if (!inited) {
        cudaGetSymbolAddress((void**)&p.Xhi, g_Xhi);
        cudaGetSymbolAddress((void**)&p.Xlo, g_Xlo);
        cudaGetSymbolAddress((void**)&p.XThi, g_XThi);
        cudaGetSymbolAddress((void**)&p.XTlo, g_XTlo);
        cudaGetSymbolAddress((void**)&p.Qhi, g_Qhi);
        cudaGetSymbolAddress((void**)&p.Qlo, g_Qlo);
        cudaGetSymbolAddress((void**)&p.Khi, g_Khi);
        cudaGetSymbolAddress((void**)&p.Klo, g_Klo);
        cudaGetSymbolAddress((void**)&p.Mhi, g_Mhi);
        cudaGetSymbolAddress((void**)&p.Mlo, g_Mlo);
        cudaGetSymbolAddress((void**)&p.Ghi, g_Ghi);
        cudaGetSymbolAddress((void**)&p.Glo, g_Glo);
        cudaGetSymbolAddress((void**)&p.Hhi, g_Hhi);
        cudaGetSymbolAddress((void**)&p.Hlo, g_Hlo);
        cudaFuncSetAttribute((const void*)mma_gemm<0, false>,
                             cudaFuncAttributeMaxDynamicSharedMemorySize, SMEM_SZ);
        cudaFuncSetAttribute((const void*)mma_gemm<1, false>,
                             cudaFuncAttributeMaxDynamicSharedMemorySize, SMEM_SZ);
        cudaFuncSetAttribute((const void*)mma_gemm<1, true>,
                             cudaFuncAttributeMaxDynamicSharedMemorySize, SMEM_SZ);
        inited = true;
    }

    const float alpha = 1.0f / sqrtf((float)D * (float)D * (float)D);
    const long long DD = (long long)D * D;
    const long long SD = (long long)S * D;

    // operand splits (X split + transpose fused in one pass)
    {
        dim3 g(S / 32, D / 32, B);
        transplit_kernel<<<g, 256>>>(X, p.Xhi, p.Xlo, p.XThi, p.XTlo);
    }
    {
        int n4 = D * D / 4;
        split_kernel<<<(n4 + 255) / 256, 256>>>(Wq, p.Qhi, p.Qlo, n4);
        split_kernel<<<(n4 + 255) / 256, 256>>>(Wk, p.Khi, p.Klo, n4);
    }

    // 1) M = Wq @ Wk^T            [768x768], K=768
    mma_gemm<1, false><<<dim3(D / 128, D / 128, 1), 256, SMEM_SZ>>>(
        p.Qhi, p.Qlo, p.Khi, p.Klo, nullptr, p.Mhi, p.Mlo, D, D, 0, 0, 0, 1.0f);
    // 2) G_b = XT_b @ XT_b^T      [768x768] x B, K=2048 — symmetric: lower
    //    triangle computed, upper mirrored in epilogue
    mma_gemm<1, true><<<dim3(D / 128, D / 128, B), 256, SMEM_SZ>>>(
        p.XThi, p.XTlo, p.XThi, p.XTlo, nullptr, p.Ghi, p.Glo, S, D, SD, SD, DD, 1.0f);
    // 3) H^T_b = (G_b @ M^T) * alpha  [768x768] x B, K=768
    mma_gemm<1, false><<<dim3(D / 128, D / 128, B), 256, SMEM_SZ>>>(
        p.Ghi, p.Glo, p.Mhi, p.Mlo, nullptr, p.Hhi, p.Hlo, D, D, DD, 0, DD, alpha);
    // 4) Out_b = X_b @ (H^T_b)^T  [2048x768] x B, K=768
    mma_gemm<0, false><<<dim3(D / 128, S / 128, B), 256, SMEM_SZ>>>(
        p.Xhi, p.Xlo, p.Hhi, p.Hlo, out, nullptr, nullptr, D, D, SD, DD, SD, 1.0f);
}